// round 1
// baseline (speedup 1.0000x reference)
#include <cuda_runtime.h>
#include <math.h>

#define D_MODEL 768
#define NHEAD   12
#define HD      64
#define HALF    32
#define LATD    256
#define BATCH   16
#define SEQ     8192
#define CHUNK   128
#define NCHUNK  (SEQ / CHUNK)     // 64
#define NCTA    (BATCH * NCHUNK)  // 1024
#define BK      32

// ---------------- scratch (static device arrays; no allocation) ----------------
__device__ float g_q[D_MODEL];                          // projected query (shared across batch)
__device__ float g_pm[NCTA * NHEAD];                    // per-chunk softmax max
__device__ float g_pl[NCTA * NHEAD];                    // per-chunk softmax sum
__device__ float g_pacc[(size_t)NCTA * NHEAD * D_MODEL];// per-chunk weighted-x accumulators (37.7 MB)
__device__ float g_hout[BATCH * D_MODEL];               // attention output (head-concat)

// ---------------- kernel A: q = Wq @ pool + bq (RoPE(pos=0) = identity) --------
__global__ void k_query(const float* __restrict__ pool,
                        const float* __restrict__ Wq,
                        const float* __restrict__ bq) {
    __shared__ float sp[D_MODEL];
    int t = threadIdx.x;
    for (int i = t; i < D_MODEL; i += 256) sp[i] = pool[i];
    __syncthreads();
    for (int o = t; o < D_MODEL; o += 256) {
        const float* w = Wq + (size_t)o * D_MODEL;
        float a = bq[o];
        for (int d = 0; d < D_MODEL; d++) a += w[d] * sp[d];
        g_q[o] = a;
    }
}

// ---------------- kernel B: fused K-GEMM + rope-scores + chunk softmax + weighted x
// grid = (NCHUNK, BATCH), 256 threads.
__global__ void __launch_bounds__(256) k_main(const float* __restrict__ x,
                                              const float* __restrict__ Wk,
                                              const float* __restrict__ bk) {
    // smem
    __shared__ float xs[CHUNK][BK];          // x tile [pos][k]   16 KB
    __shared__ float ws[BK][HD];             // Wk tile [k][dim]   8 KB
    __shared__ float sq[D_MODEL];            // query              3 KB
    __shared__ float ssc[CHUNK][NHEAD];      // scores -> probs    6 KB

    const int t  = threadIdx.x;
    const int tx = t & 15;    // dim group: dims 4*tx .. 4*tx+3 (within head)
    const int ty = t >> 4;    // pos group: positions 8*ty .. 8*ty+7
    const int p0 = ty * 8;
    const int d0 = tx * 4;

    const int chunk = blockIdx.x;
    const int b     = blockIdx.y;
    const int s0    = chunk * CHUNK;
    const float* xb = x + ((size_t)b * SEQ + s0) * D_MODEL;

    for (int i = t; i < D_MODEL; i += 256) sq[i] = g_q[i];
    for (int i = t; i < CHUNK * NHEAD; i += 256) (&ssc[0][0])[i] = 0.0f;

    // per-thread rope frequencies for its 4 dims (same for all heads)
    float invf[4];
    const float l2b = 13.287712379549449f; // log2(10000)
    #pragma unroll
    for (int j = 0; j < 4; j++) {
        int f = (d0 + j) & (HALF - 1);
        invf[j] = exp2f(-(float)f * (l2b / (float)HALF));
    }
    __syncthreads();

    // ---- phase 1: per-head GEMM + rope-weighted score reduction ----
    for (int h = 0; h < NHEAD; h++) {
        float acc[8][4];
        #pragma unroll
        for (int i = 0; i < 8; i++)
            #pragma unroll
            for (int j = 0; j < 4; j++) acc[i][j] = 0.0f;

        for (int kk = 0; kk < D_MODEL; kk += BK) {
            __syncthreads();
            // load x tile: 128x32, coalesced over k
            #pragma unroll
            for (int i = 0; i < 16; i++) {
                int idx = t + 256 * i;
                int pos = idx >> 5;
                int k   = idx & 31;
                xs[pos][k] = xb[(size_t)pos * D_MODEL + kk + k];
            }
            // load Wk tile: 64x32 for this head
            #pragma unroll
            for (int i = 0; i < 8; i++) {
                int idx = t + 256 * i;
                int dim = idx >> 5;
                int k   = idx & 31;
                ws[k][dim] = Wk[(size_t)(h * HD + dim) * D_MODEL + kk + k];
            }
            __syncthreads();

            #pragma unroll
            for (int k4 = 0; k4 < BK; k4 += 4) {
                float4 wv0 = *(const float4*)&ws[k4 + 0][d0];
                float4 wv1 = *(const float4*)&ws[k4 + 1][d0];
                float4 wv2 = *(const float4*)&ws[k4 + 2][d0];
                float4 wv3 = *(const float4*)&ws[k4 + 3][d0];
                #pragma unroll
                for (int i = 0; i < 8; i++) {
                    float4 xv = *(const float4*)&xs[p0 + i][k4];
                    acc[i][0] += xv.x * wv0.x + xv.y * wv1.x + xv.z * wv2.x + xv.w * wv3.x;
                    acc[i][1] += xv.x * wv0.y + xv.y * wv1.y + xv.z * wv2.y + xv.w * wv3.y;
                    acc[i][2] += xv.x * wv0.z + xv.y * wv1.z + xv.z * wv2.z + xv.w * wv3.z;
                    acc[i][3] += xv.x * wv0.w + xv.y * wv1.w + xv.z * wv2.w + xv.w * wv3.w;
                }
            }
        }

        // epilogue: scores[s,h] += sum_j w_rope(s,j) * (k[s,j] + bk)
        float q1[4], q2[4], bkv[4];
        #pragma unroll
        for (int j = 0; j < 4; j++) {
            int dim = d0 + j;
            bkv[j] = bk[h * HD + dim];
            if (dim < HALF) { q1[j] = sq[h * HD + dim];         q2[j] = sq[h * HD + dim + HALF]; }
            else            { q1[j] = sq[h * HD + dim - HALF];  q2[j] = sq[h * HD + dim]; }
        }
        const bool lowhalf = (d0 < HALF);  // uniform per thread

        #pragma unroll
        for (int i = 0; i < 8; i++) {
            float sg = (float)(s0 + p0 + i);
            float partial = 0.0f;
            #pragma unroll
            for (int j = 0; j < 4; j++) {
                float sn, cs;
                sincosf(sg * invf[j], &sn, &cs);
                // dim<32: weight = q1*c + q2*s ; dim>=32: weight = q2*c - q1*s
                float w = lowhalf ? (q1[j] * cs + q2[j] * sn)
                                  : (q2[j] * cs - q1[j] * sn);
                partial += w * (acc[i][j] + bkv[j]);
            }
            // reduce across the 16 tx-threads (lanes (ty&1)*16 + tx): xor over tx bits
            partial += __shfl_xor_sync(0xffffffffu, partial, 1);
            partial += __shfl_xor_sync(0xffffffffu, partial, 2);
            partial += __shfl_xor_sync(0xffffffffu, partial, 4);
            partial += __shfl_xor_sync(0xffffffffu, partial, 8);
            if (tx == 0) ssc[p0 + i][h] = partial;
        }
    }
    __syncthreads();

    // ---- phase 2: chunk-local softmax (scale + alibi) ----
    if (t < NHEAD) {
        float slope = exp2f(-2.0f * (float)(t + 1) / 3.0f);
        float m = -1e30f;
        for (int s = 0; s < CHUNK; s++) {
            float v = ssc[s][t] * 0.125f - slope * (float)(s0 + s);
            ssc[s][t] = v;
            m = fmaxf(m, v);
        }
        float l = 0.0f;
        for (int s = 0; s < CHUNK; s++) {
            float p = __expf(ssc[s][t] - m);
            ssc[s][t] = p;
            l += p;
        }
        int cta = b * NCHUNK + chunk;
        g_pm[cta * NHEAD + t] = m;
        g_pl[cta * NHEAD + t] = l;
    }
    __syncthreads();

    // ---- phase 3: weighted x accumulation: acc[h][d] = sum_s p[s,h] * x[s,d] ----
    float vacc[36];
    #pragma unroll
    for (int i = 0; i < 36; i++) vacc[i] = 0.0f;
    float* xrow = &xs[0][0];  // reuse (4096 floats >= 768)

    for (int s = 0; s < CHUNK; s++) {
        __syncthreads();
        #pragma unroll
        for (int j = 0; j < 3; j++) xrow[t + 256 * j] = xb[(size_t)s * D_MODEL + t + 256 * j];
        __syncthreads();
        float ph[NHEAD];
        #pragma unroll
        for (int hh = 0; hh < NHEAD; hh++) ph[hh] = ssc[s][hh];
        #pragma unroll
        for (int i = 0; i < 36; i++) {
            // output o = t + 256*i  ->  h = i/3, d = t + 256*(i%3)
            vacc[i] += ph[i / 3] * xrow[t + 256 * (i % 3)];
        }
    }
    {
        int cta = b * NCHUNK + chunk;
        float* dst = g_pacc + (size_t)cta * NHEAD * D_MODEL;
        #pragma unroll
        for (int i = 0; i < 36; i++) dst[t + 256 * i] = vacc[i];
    }
}

// ---------------- kernel C: merge chunks per (b,h) + Wv projection -------------
// grid = (NHEAD, BATCH), 256 threads.
__global__ void k_reduce(const float* __restrict__ Wv, const float* __restrict__ bv) {
    const int h = blockIdx.x, b = blockIdx.y, t = threadIdx.x;
    __shared__ float sx[D_MODEL];
    __shared__ float red[256];

    float m = -1e30f;
    for (int c = t; c < NCHUNK; c += 256) m = fmaxf(m, g_pm[(b * NCHUNK + c) * NHEAD + h]);
    red[t] = m; __syncthreads();
    for (int o = 128; o > 0; o >>= 1) { if (t < o) red[t] = fmaxf(red[t], red[t + o]); __syncthreads(); }
    m = red[0]; __syncthreads();

    float l = 0.0f;
    for (int c = t; c < NCHUNK; c += 256)
        l += __expf(g_pm[(b * NCHUNK + c) * NHEAD + h] - m) * g_pl[(b * NCHUNK + c) * NHEAD + h];
    red[t] = l; __syncthreads();
    for (int o = 128; o > 0; o >>= 1) { if (t < o) red[t] += red[t + o]; __syncthreads(); }
    l = red[0]; __syncthreads();
    const float inv_l = 1.0f / l;

    #pragma unroll
    for (int j = 0; j < 3; j++) {
        int d = t + 256 * j;
        float a = 0.0f;
        for (int c = 0; c < NCHUNK; c++) {
            float w = __expf(g_pm[(b * NCHUNK + c) * NHEAD + h] - m);
            a += w * g_pacc[((size_t)(b * NCHUNK + c) * NHEAD + h) * D_MODEL + d];
        }
        sx[d] = a * inv_l;
    }
    __syncthreads();

    // vout[j] = Wv[h*64+j,:] . xbar + bv  (4 lanes per output)
    int j = t >> 2, part = t & 3;
    const float* w = Wv + (size_t)(h * HD + j) * D_MODEL;
    float a = 0.0f;
    for (int d = part * 192; d < part * 192 + 192; d++) a += w[d] * sx[d];
    a += __shfl_down_sync(0xffffffffu, a, 1);
    a += __shfl_down_sync(0xffffffffu, a, 2);
    if (part == 0) g_hout[b * D_MODEL + h * HD + j] = a + bv[h * HD + j];
}

// ---------------- kernel D: pooled = Wo@out + bo ; result = Wl@pooled + bl -----
__global__ void k_final(const float* __restrict__ Wo, const float* __restrict__ bo,
                        const float* __restrict__ Wl, const float* __restrict__ bl,
                        float* __restrict__ out) {
    const int b = blockIdx.x, t = threadIdx.x;
    __shared__ float sh[D_MODEL], sp[D_MODEL];
    for (int i = t; i < D_MODEL; i += 256) sh[i] = g_hout[b * D_MODEL + i];
    __syncthreads();
    #pragma unroll
    for (int j = 0; j < 3; j++) {
        int o = t + 256 * j;
        const float* w = Wo + (size_t)o * D_MODEL;
        float a = bo[o];
        for (int d = 0; d < D_MODEL; d++) a += w[d] * sh[d];
        sp[o] = a;
    }
    __syncthreads();
    {
        const float* w = Wl + (size_t)t * D_MODEL;
        float a = bl[t];
        for (int d = 0; d < D_MODEL; d++) a += w[d] * sp[d];
        out[b * LATD + t] = a;
    }
}

// ---------------- launch --------------------------------------------------------
extern "C" void kernel_launch(void* const* d_in, const int* in_sizes, int n_in,
                              void* d_out, int out_size) {
    const float* x    = (const float*)d_in[0];
    const float* pool = (const float*)d_in[1];
    const float* Wq   = (const float*)d_in[2];
    const float* bq   = (const float*)d_in[3];
    const float* Wk   = (const float*)d_in[4];
    const float* bk   = (const float*)d_in[5];
    const float* Wv   = (const float*)d_in[6];
    const float* bv   = (const float*)d_in[7];
    const float* Wo   = (const float*)d_in[8];
    const float* bo   = (const float*)d_in[9];
    const float* Wl   = (const float*)d_in[10];
    const float* bl   = (const float*)d_in[11];
    float* out = (float*)d_out;

    k_query<<<1, 256>>>(pool, Wq, bq);
    k_main<<<dim3(NCHUNK, BATCH), 256>>>(x, Wk, bk);
    k_reduce<<<dim3(NHEAD, BATCH), 256>>>(Wv, bv);
    k_final<<<BATCH, 256>>>(Wo, bo, Wl, bl, out);
}